// round 14
// baseline (speedup 1.0000x reference)
#include <cuda_runtime.h>
#include <cuda_fp16.h>
#include <math.h>
#include <cstdint>

#define S_LEN 2048
#define DM    1024
#define NH    16
#define HD    64

// Scratch (allocation-guard rules: __device__ globals).
__device__ __half g_xh[S_LEN * DM];
__device__ __half g_wh[3][DM * DM];
__device__ __half g_qh[S_LEN * DM];
__device__ __half g_kh[S_LEN * DM];
__device__ __half g_vh[S_LEN * DM];
__device__ __half g_eh[(size_t)NH * S_LEN * S_LEN];  // unnormalized exp(scores), half
__device__ float  g_rinv[NH * S_LEN];                // 1 / rowsum

// ---------------------------------------------------------------------------
// fp32 -> fp16 converters.
// ---------------------------------------------------------------------------
__device__ __forceinline__ void cvt4(const float* __restrict__ src,
                                     __half* __restrict__ dst, size_t i)
{
    float4 v = ((const float4*)src)[i];
    __half2 a = __floats2half2_rn(v.x, v.y);
    __half2 b = __floats2half2_rn(v.z, v.w);
    uint2 u;
    u.x = *(const uint32_t*)&a;
    u.y = *(const uint32_t*)&b;
    ((uint2*)dst)[i] = u;
}

__global__ __launch_bounds__(256) void cvt_x_kernel(const float* __restrict__ X)
{
    cvt4(X, g_xh, (size_t)blockIdx.x * 256 + threadIdx.x);
}

__global__ __launch_bounds__(256) void cvt_w_kernel(
    const float* __restrict__ Wq, const float* __restrict__ Wk,
    const float* __restrict__ Wv)
{
    const float* src = (blockIdx.z == 0) ? Wq : (blockIdx.z == 1) ? Wk : Wv;
    cvt4(src, g_wh[blockIdx.z], (size_t)blockIdx.x * 256 + threadIdx.x);
}

// ---------------------------------------------------------------------------
// Kernel 1: QKV projection, raw mma.sync.m16n8k16 (unchanged from round 13).
// ---------------------------------------------------------------------------
__global__ __launch_bounds__(256) void qkv_gemm_kernel()
{
    constexpr int BM = 128, BN = 64, BK = 32;
    const __half* W = g_wh[blockIdx.z];
    __half*       Y = (blockIdx.z == 0) ? g_qh : (blockIdx.z == 1) ? g_kh : g_vh;

    __shared__ __align__(16) __half As[BM][BK + 8];   // 128 x 40
    __shared__ __align__(16) __half Bs[BK][BN + 8];   // 32 x 72

    const int tid  = threadIdx.x;
    const int warp = tid >> 5;
    const int lane = tid & 31;
    const int wm   = warp & 3;
    const int wn   = warp >> 2;

    const int row0 = blockIdx.y * BM;
    const int col0 = blockIdx.x * BN;

    float c[2][4][4];
    #pragma unroll
    for (int mi = 0; mi < 2; mi++)
        #pragma unroll
        for (int ni = 0; ni < 4; ni++)
            #pragma unroll
            for (int e = 0; e < 4; e++)
                c[mi][ni][e] = 0.0f;

    const uint32_t as = (uint32_t)__cvta_generic_to_shared(&As[0][0]);
    const uint32_t bs = (uint32_t)__cvta_generic_to_shared(&Bs[0][0]);
    const int lrow = lane & 15;
    const int lk   = (lane >> 4) * 8;

    for (int k0 = 0; k0 < DM; k0 += BK) {
        #pragma unroll
        for (int it = 0; it < 2; it++) {
            int idx = tid + it * 256;
            int r = idx >> 2, cc = idx & 3;
            *(int4*)&As[r][cc * 8] =
                *(const int4*)&g_xh[(size_t)(row0 + r) * DM + k0 + cc * 8];
        }
        {
            int r = tid >> 3, cc = tid & 7;
            *(int4*)&Bs[r][cc * 8] =
                *(const int4*)&W[(size_t)(k0 + r) * DM + col0 + cc * 8];
        }
        __syncthreads();

        #pragma unroll
        for (int kk = 0; kk < BK; kk += 16) {
            uint32_t a[2][4];
            #pragma unroll
            for (int mi = 0; mi < 2; mi++) {
                uint32_t addr = as + (uint32_t)(((wm * 32 + mi * 16 + lrow) * (BK + 8) + kk + lk) * 2);
                asm volatile(
                    "ldmatrix.sync.aligned.m8n8.x4.shared.b16 {%0,%1,%2,%3}, [%4];"
                    : "=r"(a[mi][0]), "=r"(a[mi][1]), "=r"(a[mi][2]), "=r"(a[mi][3])
                    : "r"(addr));
            }
            #pragma unroll
            for (int ni = 0; ni < 4; ni++) {
                uint32_t b0, b1;
                uint32_t addr = bs + (uint32_t)(((kk + lrow) * (BN + 8) + wn * 32 + ni * 8) * 2);
                asm volatile(
                    "ldmatrix.sync.aligned.m8n8.x2.trans.shared.b16 {%0,%1}, [%2];"
                    : "=r"(b0), "=r"(b1)
                    : "r"(addr));
                #pragma unroll
                for (int mi = 0; mi < 2; mi++) {
                    asm volatile(
                        "mma.sync.aligned.m16n8k16.row.col.f32.f16.f16.f32 "
                        "{%0,%1,%2,%3}, {%4,%5,%6,%7}, {%8,%9}, {%0,%1,%2,%3};"
                        : "+f"(c[mi][ni][0]), "+f"(c[mi][ni][1]),
                          "+f"(c[mi][ni][2]), "+f"(c[mi][ni][3])
                        : "r"(a[mi][0]), "r"(a[mi][1]), "r"(a[mi][2]), "r"(a[mi][3]),
                          "r"(b0), "r"(b1));
                }
            }
        }
        __syncthreads();
    }

    #pragma unroll
    for (int mi = 0; mi < 2; mi++) {
        int r0 = row0 + wm * 32 + mi * 16 + (lane >> 2);
        int r1 = r0 + 8;
        #pragma unroll
        for (int ni = 0; ni < 4; ni++) {
            int col = col0 + wn * 32 + ni * 8 + 2 * (lane & 3);
            __half2 lo = __floats2half2_rn(c[mi][ni][0], c[mi][ni][1]);
            __half2 hi = __floats2half2_rn(c[mi][ni][2], c[mi][ni][3]);
            *(__half2*)&Y[(size_t)r0 * DM + col] = lo;
            *(__half2*)&Y[(size_t)r1 * DM + col] = hi;
        }
    }
}

// ---------------------------------------------------------------------------
// Kernel 2 (FUSED): row-strip scores + exp + rowsum + finalize.
// One block = 128 q-rows x full 2048 k-cols for one head. grid (16, 16).
// Q tile loaded once; 16 K-tiles streamed. Row sums accumulate in registers
// across tiles; after the loop the block computes rinv, stores g_rinv, then
// finalizes its own strip (e re-read is L2-hot) writing fp32 probs via stwt.
// ---------------------------------------------------------------------------
__global__ __launch_bounds__(256) void scores_fused_kernel(float* __restrict__ probs)
{
    const int h     = blockIdx.y;
    const int qrow0 = blockIdx.x * 128;

    __shared__ __align__(16) __half Qs[128][72];                  // persistent
    __shared__ __align__(16) union {
        __half K[128][72];
        __half E[128][136];
    } u;
    __shared__ float rsum[128][2];
    __shared__ float rinv_s[128];

    const int tid  = threadIdx.x;
    const int warp = tid >> 5;
    const int lane = tid & 31;
    const int wm   = warp & 3;   // 4 strips of 32 q-rows
    const int wn   = warp >> 2;  // 2 strips of 64 k-cols

    const __half* qp = g_qh + h * HD;
    const __half* kp = g_kh + h * HD;
    __half* outp = g_eh + (size_t)h * S_LEN * S_LEN;

    // Load Q tile once.
    #pragma unroll
    for (int it = 0; it < 4; it++) {
        int idx = tid + it * 256;
        int r = idx >> 3, cc = idx & 7;
        *(int4*)&Qs[r][cc * 8] =
            *(const int4*)&qp[(size_t)(qrow0 + r) * DM + cc * 8];
    }

    const uint32_t qs = (uint32_t)__cvta_generic_to_shared(&Qs[0][0]);
    const uint32_t ks = (uint32_t)__cvta_generic_to_shared(&u.K[0][0]);
    const int lrow = lane & 15;
    const int lk   = (lane >> 4) * 8;

    float rs[2][2] = {{0.0f, 0.0f}, {0.0f, 0.0f}};   // [mi][A/B] row-sum partials

    for (int kt = 0; kt < 16; kt++) {
        const int krow0 = kt * 128;

        // Load K tile (E area from previous iter already flushed by sync below).
        __syncthreads();
        #pragma unroll
        for (int it = 0; it < 4; it++) {
            int idx = tid + it * 256;
            int r = idx >> 3, cc = idx & 7;
            *(int4*)&u.K[r][cc * 8] =
                *(const int4*)&kp[(size_t)(krow0 + r) * DM + cc * 8];
        }
        __syncthreads();

        float c[2][8][4];
        #pragma unroll
        for (int mi = 0; mi < 2; mi++)
            #pragma unroll
            for (int ni = 0; ni < 8; ni++)
                #pragma unroll
                for (int e = 0; e < 4; e++)
                    c[mi][ni][e] = 0.0f;

        #pragma unroll
        for (int kk = 0; kk < HD; kk += 16) {
            uint32_t a[2][4];
            #pragma unroll
            for (int mi = 0; mi < 2; mi++) {
                uint32_t addr = qs + (uint32_t)(((wm * 32 + mi * 16 + lrow) * 72 + kk + lk) * 2);
                asm volatile(
                    "ldmatrix.sync.aligned.m8n8.x4.shared.b16 {%0,%1,%2,%3}, [%4];"
                    : "=r"(a[mi][0]), "=r"(a[mi][1]), "=r"(a[mi][2]), "=r"(a[mi][3])
                    : "r"(addr));
            }
            #pragma unroll
            for (int nb = 0; nb < 4; nb++) {
                uint32_t b0, b1, b2, b3;
                uint32_t addr = ks + (uint32_t)(((wn * 64 + nb * 16 + lrow) * 72 + kk + lk) * 2);
                asm volatile(
                    "ldmatrix.sync.aligned.m8n8.x4.shared.b16 {%0,%1,%2,%3}, [%4];"
                    : "=r"(b0), "=r"(b1), "=r"(b2), "=r"(b3)
                    : "r"(addr));
                #pragma unroll
                for (int mi = 0; mi < 2; mi++) {
                    asm volatile(
                        "mma.sync.aligned.m16n8k16.row.col.f32.f16.f16.f32 "
                        "{%0,%1,%2,%3}, {%4,%5,%6,%7}, {%8,%9}, {%0,%1,%2,%3};"
                        : "+f"(c[mi][2 * nb][0]), "+f"(c[mi][2 * nb][1]),
                          "+f"(c[mi][2 * nb][2]), "+f"(c[mi][2 * nb][3])
                        : "r"(a[mi][0]), "r"(a[mi][1]), "r"(a[mi][2]), "r"(a[mi][3]),
                          "r"(b0), "r"(b2));
                    asm volatile(
                        "mma.sync.aligned.m16n8k16.row.col.f32.f16.f16.f32 "
                        "{%0,%1,%2,%3}, {%4,%5,%6,%7}, {%8,%9}, {%0,%1,%2,%3};"
                        : "+f"(c[mi][2 * nb + 1][0]), "+f"(c[mi][2 * nb + 1][1]),
                          "+f"(c[mi][2 * nb + 1][2]), "+f"(c[mi][2 * nb + 1][3])
                        : "r"(a[mi][0]), "r"(a[mi][1]), "r"(a[mi][2]), "r"(a[mi][3]),
                          "r"(b1), "r"(b3));
                }
            }
        }
        __syncthreads();   // K consumed; E area may be written

        // exp in registers + accumulate running row-sum partials.
        #pragma unroll
        for (int mi = 0; mi < 2; mi++) {
            #pragma unroll
            for (int ni = 0; ni < 8; ni++) {
                #pragma unroll
                for (int e = 0; e < 4; e++)
                    c[mi][ni][e] = __expf(c[mi][ni][e] * 0.125f);
                rs[mi][0] += c[mi][ni][0] + c[mi][ni][1];
                rs[mi][1] += c[mi][ni][2] + c[mi][ni][3];
            }
        }

        // Stage half e-tile.
        #pragma unroll
        for (int mi = 0; mi < 2; mi++)
            #pragma unroll
            for (int ni = 0; ni < 8; ni++) {
                int r   = wm * 32 + mi * 16 + (lane >> 2);
                int col = wn * 64 + ni * 8 + 2 * (lane & 3);
                __half2 lo = __floats2half2_rn(c[mi][ni][0], c[mi][ni][1]);
                __half2 hi = __floats2half2_rn(c[mi][ni][2], c[mi][ni][3]);
                *(__half2*)&u.E[r][col]     = lo;
                *(__half2*)&u.E[r + 8][col] = hi;
            }
        __syncthreads();

        // Coalesced write of half e-tile.
        #pragma unroll
        for (int it = 0; it < 8; it++) {
            int idx = tid + it * 256;
            int r = idx >> 4, cc = idx & 15;
            uint4 o = *(const uint4*)&u.E[r][cc * 8];
            *(uint4*)&outp[(size_t)(qrow0 + r) * S_LEN + krow0 + cc * 8] = o;
        }
    }

    // Row-sum combine: shfl over the 4-lane row group, then across wn halves.
    #pragma unroll
    for (int mi = 0; mi < 2; mi++) {
        float sA = rs[mi][0], sB = rs[mi][1];
        sA += __shfl_xor_sync(0xFFFFFFFFu, sA, 1);
        sA += __shfl_xor_sync(0xFFFFFFFFu, sA, 2);
        sB += __shfl_xor_sync(0xFFFFFFFFu, sB, 1);
        sB += __shfl_xor_sync(0xFFFFFFFFu, sB, 2);
        if ((lane & 3) == 0) {
            int r = wm * 32 + mi * 16 + (lane >> 2);
            rsum[r][wn]     = sA;
            rsum[r + 8][wn] = sB;
        }
    }
    __syncthreads();
    if (tid < 128) {
        float iv = 1.0f / (rsum[tid][0] + rsum[tid][1]);
        rinv_s[tid] = iv;
        g_rinv[(size_t)h * S_LEN + qrow0 + tid] = iv;
    }
    __syncthreads();

    // Finalize this strip: e (L2-hot) -> normalized fp32 probs.
    const uint4* src = (const uint4*)(outp + (size_t)qrow0 * S_LEN);
    float* dst = probs + (size_t)h * S_LEN * S_LEN + (size_t)qrow0 * S_LEN;
    #pragma unroll 4
    for (int it = 0; it < 128; it++) {
        int ci = tid + it * 256;            // 32768 chunks of 8 halfs
        float iv = rinv_s[ci >> 8];         // 256 chunks per row
        uint4 uv = src[ci];
        __half2 h0 = *(const __half2*)&uv.x;
        __half2 h1 = *(const __half2*)&uv.y;
        __half2 h2 = *(const __half2*)&uv.z;
        __half2 h3 = *(const __half2*)&uv.w;
        float2 f0 = __half22float2(h0);
        float2 f1 = __half22float2(h1);
        float2 f2 = __half22float2(h2);
        float2 f3 = __half22float2(h3);
        __stwt((float4*)(dst + (size_t)ci * 8),
               make_float4(f0.x * iv, f0.y * iv, f1.x * iv, f1.y * iv));
        __stwt((float4*)(dst + (size_t)ci * 8 + 4),
               make_float4(f2.x * iv, f2.y * iv, f3.x * iv, f3.y * iv));
    }
}

// ---------------------------------------------------------------------------
// Kernel 3: PV, raw mma.sync (unchanged from round 12).
// ---------------------------------------------------------------------------
__global__ __launch_bounds__(256) void pv_kernel(float* __restrict__ ctx)
{
    constexpr int BM = 128, BK = 64;
    const int h = blockIdx.y;
    const __half* E  = g_eh + (size_t)h * S_LEN * S_LEN;
    const __half* vp = g_vh + h * HD;

    __shared__ __align__(16) __half Ps[BM][BK + 8];   // 128 x 72
    __shared__ __align__(16) __half Vs[BK][HD + 8];   // 64 x 72
    __shared__ float rinv[BM];

    const int tid  = threadIdx.x;
    const int warp = tid >> 5;
    const int lane = tid & 31;
    const int wm   = warp & 3;
    const int wn   = warp >> 2;
    const int row0 = blockIdx.x * BM;

    if (tid < BM)
        rinv[tid] = g_rinv[(size_t)h * S_LEN + row0 + tid];

    float c[2][4][4];
    #pragma unroll
    for (int mi = 0; mi < 2; mi++)
        #pragma unroll
        for (int ni = 0; ni < 4; ni++)
            #pragma unroll
            for (int e = 0; e < 4; e++)
                c[mi][ni][e] = 0.0f;

    const uint32_t ps = (uint32_t)__cvta_generic_to_shared(&Ps[0][0]);
    const uint32_t vs = (uint32_t)__cvta_generic_to_shared(&Vs[0][0]);
    const int lrow = lane & 15;
    const int lk   = (lane >> 4) * 8;

    for (int k0 = 0; k0 < S_LEN; k0 += BK) {
        #pragma unroll
        for (int it = 0; it < 4; it++) {
            int idx = tid + it * 256;
            int r = idx >> 3, cc = idx & 7;
            *(int4*)&Ps[r][cc * 8] =
                *(const int4*)&E[(size_t)(row0 + r) * S_LEN + k0 + cc * 8];
        }
        #pragma unroll
        for (int it = 0; it < 2; it++) {
            int idx = tid + it * 256;
            int r = idx >> 3, cc = idx & 7;
            *(int4*)&Vs[r][cc * 8] =
                *(const int4*)&vp[(size_t)(k0 + r) * DM + cc * 8];
        }
        __syncthreads();

        #pragma unroll
        for (int kk = 0; kk < BK; kk += 16) {
            uint32_t a[2][4];
            #pragma unroll
            for (int mi = 0; mi < 2; mi++) {
                uint32_t addr = ps + (uint32_t)(((wm * 32 + mi * 16 + lrow) * 72 + kk + lk) * 2);
                asm volatile(
                    "ldmatrix.sync.aligned.m8n8.x4.shared.b16 {%0,%1,%2,%3}, [%4];"
                    : "=r"(a[mi][0]), "=r"(a[mi][1]), "=r"(a[mi][2]), "=r"(a[mi][3])
                    : "r"(addr));
            }
            #pragma unroll
            for (int ni = 0; ni < 4; ni++) {
                uint32_t b0, b1;
                uint32_t addr = vs + (uint32_t)(((kk + lrow) * 72 + wn * 32 + ni * 8) * 2);
                asm volatile(
                    "ldmatrix.sync.aligned.m8n8.x2.trans.shared.b16 {%0,%1}, [%2];"
                    : "=r"(b0), "=r"(b1)
                    : "r"(addr));
                #pragma unroll
                for (int mi = 0; mi < 2; mi++) {
                    asm volatile(
                        "mma.sync.aligned.m16n8k16.row.col.f32.f16.f16.f32 "
                        "{%0,%1,%2,%3}, {%4,%5,%6,%7}, {%8,%9}, {%0,%1,%2,%3};"
                        : "+f"(c[mi][ni][0]), "+f"(c[mi][ni][1]),
                          "+f"(c[mi][ni][2]), "+f"(c[mi][ni][3])
                        : "r"(a[mi][0]), "r"(a[mi][1]), "r"(a[mi][2]), "r"(a[mi][3]),
                          "r"(b0), "r"(b1));
                }
            }
        }
        __syncthreads();
    }

    #pragma unroll
    for (int mi = 0; mi < 2; mi++) {
        int rloc0 = wm * 32 + mi * 16 + (lane >> 2);
        int rloc1 = rloc0 + 8;
        float iv0 = rinv[rloc0];
        float iv1 = rinv[rloc1];
        #pragma unroll
        for (int ni = 0; ni < 4; ni++) {
            int col = h * HD + wn * 32 + ni * 8 + 2 * (lane & 3);
            *(float2*)&ctx[(size_t)(row0 + rloc0) * DM + col] =
                make_float2(c[mi][ni][0] * iv0, c[mi][ni][1] * iv0);
            *(float2*)&ctx[(size_t)(row0 + rloc1) * DM + col] =
                make_float2(c[mi][ni][2] * iv1, c[mi][ni][3] * iv1);
        }
    }
}

// ---------------------------------------------------------------------------
// Launch. d_out layout: context (2048*1024 floats) then probs (16*2048*2048).
// ---------------------------------------------------------------------------
extern "C" void kernel_launch(void* const* d_in, const int* in_sizes, int n_in,
                              void* d_out, int out_size)
{
    const float* hs = (const float*)d_in[0];
    const float* Wq = (const float*)d_in[1];
    const float* Wk = (const float*)d_in[2];
    const float* Wv = (const float*)d_in[3];

    float* ctx   = (float*)d_out;
    float* probs = ctx + (size_t)S_LEN * DM;

    cvt_x_kernel<<<dim3(S_LEN * DM / 4 / 256), 256>>>(hs);
    cvt_w_kernel<<<dim3(DM * DM / 4 / 256, 1, 3), 256>>>(Wq, Wk, Wv);
    qkv_gemm_kernel<<<dim3(DM / 64, S_LEN / 128, 3), 256>>>();
    scores_fused_kernel<<<dim3(S_LEN / 128, NH), 256>>>(probs);
    pv_kernel<<<dim3(S_LEN / 128, NH), 256>>>(ctx);
}

// round 15
// speedup vs baseline: 1.1959x; 1.1959x over previous
#include <cuda_runtime.h>
#include <cuda_fp16.h>
#include <math.h>
#include <cstdint>

#define S_LEN 2048
#define DM    1024
#define NH    16
#define HD    64

// Scratch (allocation-guard rules: __device__ globals).
__device__ __half g_xh[S_LEN * DM];
__device__ __half g_wh[3][DM * DM];
__device__ __half g_qh[S_LEN * DM];
__device__ __half g_kh[S_LEN * DM];
__device__ __half g_vh[S_LEN * DM];
__device__ __half g_eh[(size_t)NH * S_LEN * S_LEN];  // unnormalized exp(scores), half
__device__ float  g_psum[(size_t)NH * S_LEN * 32];   // per-(row, ktile, wn) partials
__device__ float  g_rinv[NH * S_LEN];                // 1 / rowsum

#define CP_ASYNC16(saddr, gptr)                                               \
    asm volatile("cp.async.cg.shared.global [%0], [%1], 16;"                  \
                 :: "r"(saddr), "l"(gptr) : "memory")
#define CP_COMMIT() asm volatile("cp.async.commit_group;" ::: "memory")

// ---------------------------------------------------------------------------
// fp32 -> fp16 converter (X + all three W in one launch).
// ---------------------------------------------------------------------------
__device__ __forceinline__ void cvt4(const float* __restrict__ src,
                                     __half* __restrict__ dst, size_t i)
{
    float4 v = ((const float4*)src)[i];
    __half2 a = __floats2half2_rn(v.x, v.y);
    __half2 b = __floats2half2_rn(v.z, v.w);
    uint2 u;
    u.x = *(const uint32_t*)&a;
    u.y = *(const uint32_t*)&b;
    ((uint2*)dst)[i] = u;
}

__global__ __launch_bounds__(256) void cvt_all_kernel(
    const float* __restrict__ X,  const float* __restrict__ Wq,
    const float* __restrict__ Wk, const float* __restrict__ Wv)
{
    int b = blockIdx.x;
    if (b < 2048) {
        cvt4(X, g_xh, (size_t)b * 256 + threadIdx.x);
    } else {
        b -= 2048;
        int w  = b >> 10;       // 1024 blocks per W
        int bb = b & 1023;
        const float* src = (w == 0) ? Wq : (w == 1) ? Wk : Wv;
        cvt4(src, g_wh[w], (size_t)bb * 256 + threadIdx.x);
    }
}

// ---------------------------------------------------------------------------
// Kernel 1: QKV projection, raw mma.sync.m16n8k16 (unchanged from round 13).
// ---------------------------------------------------------------------------
__global__ __launch_bounds__(256) void qkv_gemm_kernel()
{
    constexpr int BM = 128, BN = 64, BK = 32;
    const __half* W = g_wh[blockIdx.z];
    __half*       Y = (blockIdx.z == 0) ? g_qh : (blockIdx.z == 1) ? g_kh : g_vh;

    __shared__ __align__(16) __half As[BM][BK + 8];   // 128 x 40
    __shared__ __align__(16) __half Bs[BK][BN + 8];   // 32 x 72

    const int tid  = threadIdx.x;
    const int warp = tid >> 5;
    const int lane = tid & 31;
    const int wm   = warp & 3;
    const int wn   = warp >> 2;

    const int row0 = blockIdx.y * BM;
    const int col0 = blockIdx.x * BN;

    float c[2][4][4];
    #pragma unroll
    for (int mi = 0; mi < 2; mi++)
        #pragma unroll
        for (int ni = 0; ni < 4; ni++)
            #pragma unroll
            for (int e = 0; e < 4; e++)
                c[mi][ni][e] = 0.0f;

    const uint32_t as = (uint32_t)__cvta_generic_to_shared(&As[0][0]);
    const uint32_t bs = (uint32_t)__cvta_generic_to_shared(&Bs[0][0]);
    const int lrow = lane & 15;
    const int lk   = (lane >> 4) * 8;

    for (int k0 = 0; k0 < DM; k0 += BK) {
        #pragma unroll
        for (int it = 0; it < 2; it++) {
            int idx = tid + it * 256;
            int r = idx >> 2, cc = idx & 3;
            *(int4*)&As[r][cc * 8] =
                *(const int4*)&g_xh[(size_t)(row0 + r) * DM + k0 + cc * 8];
        }
        {
            int r = tid >> 3, cc = tid & 7;
            *(int4*)&Bs[r][cc * 8] =
                *(const int4*)&W[(size_t)(k0 + r) * DM + col0 + cc * 8];
        }
        __syncthreads();

        #pragma unroll
        for (int kk = 0; kk < BK; kk += 16) {
            uint32_t a[2][4];
            #pragma unroll
            for (int mi = 0; mi < 2; mi++) {
                uint32_t addr = as + (uint32_t)(((wm * 32 + mi * 16 + lrow) * (BK + 8) + kk + lk) * 2);
                asm volatile(
                    "ldmatrix.sync.aligned.m8n8.x4.shared.b16 {%0,%1,%2,%3}, [%4];"
                    : "=r"(a[mi][0]), "=r"(a[mi][1]), "=r"(a[mi][2]), "=r"(a[mi][3])
                    : "r"(addr));
            }
            #pragma unroll
            for (int ni = 0; ni < 4; ni++) {
                uint32_t b0, b1;
                uint32_t addr = bs + (uint32_t)(((kk + lrow) * (BN + 8) + wn * 32 + ni * 8) * 2);
                asm volatile(
                    "ldmatrix.sync.aligned.m8n8.x2.trans.shared.b16 {%0,%1}, [%2];"
                    : "=r"(b0), "=r"(b1)
                    : "r"(addr));
                #pragma unroll
                for (int mi = 0; mi < 2; mi++) {
                    asm volatile(
                        "mma.sync.aligned.m16n8k16.row.col.f32.f16.f16.f32 "
                        "{%0,%1,%2,%3}, {%4,%5,%6,%7}, {%8,%9}, {%0,%1,%2,%3};"
                        : "+f"(c[mi][ni][0]), "+f"(c[mi][ni][1]),
                          "+f"(c[mi][ni][2]), "+f"(c[mi][ni][3])
                        : "r"(a[mi][0]), "r"(a[mi][1]), "r"(a[mi][2]), "r"(a[mi][3]),
                          "r"(b0), "r"(b1));
                }
            }
        }
        __syncthreads();
    }

    #pragma unroll
    for (int mi = 0; mi < 2; mi++) {
        int r0 = row0 + wm * 32 + mi * 16 + (lane >> 2);
        int r1 = r0 + 8;
        #pragma unroll
        for (int ni = 0; ni < 4; ni++) {
            int col = col0 + wn * 32 + ni * 8 + 2 * (lane & 3);
            __half2 lo = __floats2half2_rn(c[mi][ni][0], c[mi][ni][1]);
            __half2 hi = __floats2half2_rn(c[mi][ni][2], c[mi][ni][3]);
            *(__half2*)&Y[(size_t)r0 * DM + col] = lo;
            *(__half2*)&Y[(size_t)r1 * DM + col] = hi;
        }
    }
}

// ---------------------------------------------------------------------------
// Kernel 2: e = exp(q.k/8), raw mma.sync (unchanged from round 12).
// ---------------------------------------------------------------------------
__global__ __launch_bounds__(256) void scores_exp_kernel()
{
    const int h = blockIdx.z;
    __shared__ __align__(16) union {
        struct { __half Q[128][72]; __half K[128][72]; } in;
        __half E[128][136];
    } u;

    const int tid  = threadIdx.x;
    const int warp = tid >> 5;
    const int lane = tid & 31;
    const int wm   = warp & 3;
    const int wn   = warp >> 2;

    const int qrow0 = blockIdx.y * 128;
    const int krow0 = blockIdx.x * 128;
    const __half* qp = g_qh + h * HD;
    const __half* kp = g_kh + h * HD;

    #pragma unroll
    for (int it = 0; it < 4; it++) {
        int idx = tid + it * 256;
        int r = idx >> 3, c = idx & 7;
        *(int4*)&u.in.Q[r][c * 8] =
            *(const int4*)&qp[(size_t)(qrow0 + r) * DM + c * 8];
        *(int4*)&u.in.K[r][c * 8] =
            *(const int4*)&kp[(size_t)(krow0 + r) * DM + c * 8];
    }
    __syncthreads();

    float c[2][8][4];
    #pragma unroll
    for (int mi = 0; mi < 2; mi++)
        #pragma unroll
        for (int ni = 0; ni < 8; ni++)
            #pragma unroll
            for (int e = 0; e < 4; e++)
                c[mi][ni][e] = 0.0f;

    const uint32_t qs = (uint32_t)__cvta_generic_to_shared(&u.in.Q[0][0]);
    const uint32_t ks = (uint32_t)__cvta_generic_to_shared(&u.in.K[0][0]);
    const int lrow = lane & 15;
    const int lk   = (lane >> 4) * 8;

    #pragma unroll
    for (int kk = 0; kk < HD; kk += 16) {
        uint32_t a[2][4];
        #pragma unroll
        for (int mi = 0; mi < 2; mi++) {
            uint32_t addr = qs + (uint32_t)(((wm * 32 + mi * 16 + lrow) * 72 + kk + lk) * 2);
            asm volatile(
                "ldmatrix.sync.aligned.m8n8.x4.shared.b16 {%0,%1,%2,%3}, [%4];"
                : "=r"(a[mi][0]), "=r"(a[mi][1]), "=r"(a[mi][2]), "=r"(a[mi][3])
                : "r"(addr));
        }
        #pragma unroll
        for (int nb = 0; nb < 4; nb++) {
            uint32_t b0, b1, b2, b3;
            uint32_t addr = ks + (uint32_t)(((wn * 64 + nb * 16 + lrow) * 72 + kk + lk) * 2);
            asm volatile(
                "ldmatrix.sync.aligned.m8n8.x4.shared.b16 {%0,%1,%2,%3}, [%4];"
                : "=r"(b0), "=r"(b1), "=r"(b2), "=r"(b3)
                : "r"(addr));
            #pragma unroll
            for (int mi = 0; mi < 2; mi++) {
                asm volatile(
                    "mma.sync.aligned.m16n8k16.row.col.f32.f16.f16.f32 "
                    "{%0,%1,%2,%3}, {%4,%5,%6,%7}, {%8,%9}, {%0,%1,%2,%3};"
                    : "+f"(c[mi][2 * nb][0]), "+f"(c[mi][2 * nb][1]),
                      "+f"(c[mi][2 * nb][2]), "+f"(c[mi][2 * nb][3])
                    : "r"(a[mi][0]), "r"(a[mi][1]), "r"(a[mi][2]), "r"(a[mi][3]),
                      "r"(b0), "r"(b2));
                asm volatile(
                    "mma.sync.aligned.m16n8k16.row.col.f32.f16.f16.f32 "
                    "{%0,%1,%2,%3}, {%4,%5,%6,%7}, {%8,%9}, {%0,%1,%2,%3};"
                    : "+f"(c[mi][2 * nb + 1][0]), "+f"(c[mi][2 * nb + 1][1]),
                      "+f"(c[mi][2 * nb + 1][2]), "+f"(c[mi][2 * nb + 1][3])
                    : "r"(a[mi][0]), "r"(a[mi][1]), "r"(a[mi][2]), "r"(a[mi][3]),
                      "r"(b1), "r"(b3));
            }
        }
    }
    __syncthreads();

    #pragma unroll
    for (int mi = 0; mi < 2; mi++) {
        float sA = 0.0f, sB = 0.0f;
        #pragma unroll
        for (int ni = 0; ni < 8; ni++) {
            #pragma unroll
            for (int e = 0; e < 4; e++)
                c[mi][ni][e] = __expf(c[mi][ni][e] * 0.125f);
            sA += c[mi][ni][0] + c[mi][ni][1];
            sB += c[mi][ni][2] + c[mi][ni][3];
        }
        sA += __shfl_xor_sync(0xFFFFFFFFu, sA, 1);
        sA += __shfl_xor_sync(0xFFFFFFFFu, sA, 2);
        sB += __shfl_xor_sync(0xFFFFFFFFu, sB, 1);
        sB += __shfl_xor_sync(0xFFFFFFFFu, sB, 2);
        if ((lane & 3) == 0) {
            int r = wm * 32 + mi * 16 + (lane >> 2);
            g_psum[((size_t)h * S_LEN + qrow0 + r) * 32 + blockIdx.x * 2 + wn] = sA;
            g_psum[((size_t)h * S_LEN + qrow0 + r + 8) * 32 + blockIdx.x * 2 + wn] = sB;
        }
    }

    #pragma unroll
    for (int mi = 0; mi < 2; mi++)
        #pragma unroll
        for (int ni = 0; ni < 8; ni++) {
            int r   = wm * 32 + mi * 16 + (lane >> 2);
            int col = wn * 64 + ni * 8 + 2 * (lane & 3);
            __half2 lo = __floats2half2_rn(c[mi][ni][0], c[mi][ni][1]);
            __half2 hi = __floats2half2_rn(c[mi][ni][2], c[mi][ni][3]);
            *(__half2*)&u.E[r][col]     = lo;
            *(__half2*)&u.E[r + 8][col] = hi;
        }
    __syncthreads();

    __half* outp = g_eh + (size_t)h * S_LEN * S_LEN;
    #pragma unroll
    for (int it = 0; it < 8; it++) {
        int idx = tid + it * 256;
        int r = idx >> 4, cc = idx & 15;
        uint4 o = *(const uint4*)&u.E[r][cc * 8];
        *(uint4*)&outp[(size_t)(qrow0 + r) * S_LEN + krow0 + cc * 8] = o;
    }
}

// ---------------------------------------------------------------------------
// Kernel 3: rowsum -> reciprocal.
// ---------------------------------------------------------------------------
__global__ __launch_bounds__(256) void rowsum_kernel()
{
    int row = blockIdx.x * 256 + threadIdx.x;
    const float* p = &g_psum[(size_t)row * 32];
    float s = 0.0f;
    #pragma unroll
    for (int i = 0; i < 32; i++) s += p[i];
    g_rinv[row] = 1.0f / s;
}

// ---------------------------------------------------------------------------
// Kernel 4: finalize probs with streaming (__stwt) stores.
// ---------------------------------------------------------------------------
__global__ __launch_bounds__(256) void finalize_kernel(float* __restrict__ probs)
{
    const size_t row = blockIdx.x;
    const float rinv = g_rinv[row];
    const uint4* src = (const uint4*)(g_eh + row * S_LEN);
    float4* dst = (float4*)(probs + row * S_LEN);
    const int tid = threadIdx.x;

    uint4 uv = src[tid];
    __half2 h0 = *(const __half2*)&uv.x;
    __half2 h1 = *(const __half2*)&uv.y;
    __half2 h2 = *(const __half2*)&uv.z;
    __half2 h3 = *(const __half2*)&uv.w;
    float2 f0 = __half22float2(h0);
    float2 f1 = __half22float2(h1);
    float2 f2 = __half22float2(h2);
    float2 f3 = __half22float2(h3);
    __stwt(&dst[2 * tid],
           make_float4(f0.x * rinv, f0.y * rinv, f1.x * rinv, f1.y * rinv));
    __stwt(&dst[2 * tid + 1],
           make_float4(f2.x * rinv, f2.y * rinv, f3.x * rinv, f3.y * rinv));
}

// ---------------------------------------------------------------------------
// Kernel 5: PV, raw mma.sync + cp.async double-buffered tile pipeline.
// BM=128, BK=64, 32 K-stages. 8 warps (4 m-strips x 2 n-strips of 32 cols).
// ---------------------------------------------------------------------------
__global__ __launch_bounds__(256) void pv_kernel(float* __restrict__ ctx)
{
    constexpr int BM = 128, BK = 64, NSTAGE = S_LEN / BK;   // 32
    const int h = blockIdx.y;
    const __half* E  = g_eh + (size_t)h * S_LEN * S_LEN;
    const __half* vp = g_vh + h * HD;

    __shared__ __align__(16) __half Ps[2][BM][BK + 8];   // 2 x 128 x 72
    __shared__ __align__(16) __half Vs[2][BK][HD + 8];   // 2 x 64 x 72
    __shared__ float rinv[BM];

    const int tid  = threadIdx.x;
    const int warp = tid >> 5;
    const int lane = tid & 31;
    const int wm   = warp & 3;
    const int wn   = warp >> 2;
    const int row0 = blockIdx.x * BM;

    if (tid < BM)
        rinv[tid] = g_rinv[(size_t)h * S_LEN + row0 + tid];

    float c[2][4][4];
    #pragma unroll
    for (int mi = 0; mi < 2; mi++)
        #pragma unroll
        for (int ni = 0; ni < 4; ni++)
            #pragma unroll
            for (int e = 0; e < 4; e++)
                c[mi][ni][e] = 0.0f;

    const uint32_t ps0 = (uint32_t)__cvta_generic_to_shared(&Ps[0][0][0]);
    const uint32_t ps1 = (uint32_t)__cvta_generic_to_shared(&Ps[1][0][0]);
    const uint32_t vs0 = (uint32_t)__cvta_generic_to_shared(&Vs[0][0][0]);
    const uint32_t vs1 = (uint32_t)__cvta_generic_to_shared(&Vs[1][0][0]);
    const int lrow = lane & 15;
    const int lk   = (lane >> 4) * 8;

    // Issue async copies for one stage into one buffer.
    auto issue = [&](int stage, int buf) {
        const int k0 = stage * BK;
        const uint32_t pb = buf ? ps1 : ps0;
        const uint32_t vb = buf ? vs1 : vs0;
        #pragma unroll
        for (int it = 0; it < 4; it++) {          // P: 1024 chunks of 16B
            int idx = tid + it * 256;
            int r = idx >> 3, cc = idx & 7;
            CP_ASYNC16(pb + (uint32_t)((r * (BK + 8) + cc * 8) * 2),
                       &E[(size_t)(row0 + r) * S_LEN + k0 + cc * 8]);
        }
        #pragma unroll
        for (int it = 0; it < 2; it++) {          // V: 512 chunks of 16B
            int idx = tid + it * 256;
            int r = idx >> 3, cc = idx & 7;
            CP_ASYNC16(vb + (uint32_t)((r * (HD + 8) + cc * 8) * 2),
                       &vp[(size_t)(k0 + r) * DM + cc * 8]);
        }
    };

    issue(0, 0);
    CP_COMMIT();

    for (int i = 0; i < NSTAGE; i++) {
        const int buf = i & 1;
        if (i + 1 < NSTAGE) {
            issue(i + 1, buf ^ 1);
            CP_COMMIT();
            asm volatile("cp.async.wait_group 1;" ::: "memory");
        } else {
            asm volatile("cp.async.wait_group 0;" ::: "memory");
        }
        __syncthreads();

        const uint32_t pb = buf ? ps1 : ps0;
        const uint32_t vb = buf ? vs1 : vs0;
        #pragma unroll
        for (int kk = 0; kk < BK; kk += 16) {
            uint32_t a[2][4];
            #pragma unroll
            for (int mi = 0; mi < 2; mi++) {
                uint32_t addr = pb + (uint32_t)(((wm * 32 + mi * 16 + lrow) * (BK + 8) + kk + lk) * 2);
                asm volatile(
                    "ldmatrix.sync.aligned.m8n8.x4.shared.b16 {%0,%1,%2,%3}, [%4];"
                    : "=r"(a[mi][0]), "=r"(a[mi][1]), "=r"(a[mi][2]), "=r"(a[mi][3])
                    : "r"(addr));
            }
            #pragma unroll
            for (int ni = 0; ni < 4; ni++) {
                uint32_t b0, b1;
                uint32_t addr = vb + (uint32_t)(((kk + lrow) * (HD + 8) + wn * 32 + ni * 8) * 2);
                asm volatile(
                    "ldmatrix.sync.aligned.m8n8.x2.trans.shared.b16 {%0,%1}, [%2];"
                    : "=r"(b0), "=r"(b1)
                    : "r"(addr));
                #pragma unroll
                for (int mi = 0; mi < 2; mi++) {
                    asm volatile(
                        "mma.sync.aligned.m16n8k16.row.col.f32.f16.f16.f32 "
                        "{%0,%1,%2,%3}, {%4,%5,%6,%7}, {%8,%9}, {%0,%1,%2,%3};"
                        : "+f"(c[mi][ni][0]), "+f"(c[mi][ni][1]),
                          "+f"(c[mi][ni][2]), "+f"(c[mi][ni][3])
                        : "r"(a[mi][0]), "r"(a[mi][1]), "r"(a[mi][2]), "r"(a[mi][3]),
                          "r"(b0), "r"(b1));
                }
            }
        }
        __syncthreads();   // all warps done reading buf before it's refilled
    }

    #pragma unroll
    for (int mi = 0; mi < 2; mi++) {
        int rloc0 = wm * 32 + mi * 16 + (lane >> 2);
        int rloc1 = rloc0 + 8;
        float iv0 = rinv[rloc0];
        float iv1 = rinv[rloc1];
        #pragma unroll
        for (int ni = 0; ni < 4; ni++) {
            int col = h * HD + wn * 32 + ni * 8 + 2 * (lane & 3);
            *(float2*)&ctx[(size_t)(row0 + rloc0) * DM + col] =
                make_float2(c[mi][ni][0] * iv0, c[mi][ni][1] * iv0);
            *(float2*)&ctx[(size_t)(row0 + rloc1) * DM + col] =
                make_float2(c[mi][ni][2] * iv1, c[mi][ni][3] * iv1);
        }
    }
}

// ---------------------------------------------------------------------------
// Launch. d_out layout: context (2048*1024 floats) then probs (16*2048*2048).
// ---------------------------------------------------------------------------
extern "C" void kernel_launch(void* const* d_in, const int* in_sizes, int n_in,
                              void* d_out, int out_size)
{
    const float* hs = (const float*)d_in[0];
    const float* Wq = (const float*)d_in[1];
    const float* Wk = (const float*)d_in[2];
    const float* Wv = (const float*)d_in[3];

    float* ctx   = (float*)d_out;
    float* probs = ctx + (size_t)S_LEN * DM;

    cvt_all_kernel<<<dim3(5120), 256>>>(hs, Wq, Wk, Wv);
    qkv_gemm_kernel<<<dim3(DM / 64, S_LEN / 128, 3), 256>>>();
    scores_exp_kernel<<<dim3(S_LEN / 128, S_LEN / 128, NH), 256>>>();
    rowsum_kernel<<<dim3(NH * S_LEN / 256), 256>>>();
    pv_kernel<<<dim3(S_LEN / 128, NH), 256>>>(ctx);
    finalize_kernel<<<dim3(NH * S_LEN), 256>>>(probs);
}

// round 16
// speedup vs baseline: 1.2910x; 1.0795x over previous
#include <cuda_runtime.h>
#include <cuda_fp16.h>
#include <math.h>
#include <cstdint>

#define S_LEN 2048
#define DM    1024
#define NH    16
#define HD    64

// Scratch (allocation-guard rules: __device__ globals).
__device__ __half g_xh[S_LEN * DM];
__device__ __half g_wh[3][DM * DM];
__device__ __half g_qh[S_LEN * DM];
__device__ __half g_kh[S_LEN * DM];
__device__ __half g_vh[S_LEN * DM];
__device__ __half g_eh[(size_t)NH * S_LEN * S_LEN];  // unnormalized exp(scores), half
__device__ float  g_psum[(size_t)NH * S_LEN * 32];   // per-(row, ktile, wn) partials
__device__ float  g_rinv[NH * S_LEN];                // 1 / rowsum

#define CP_ASYNC16(saddr, gptr)                                               \
    asm volatile("cp.async.cg.shared.global [%0], [%1], 16;"                  \
                 :: "r"(saddr), "l"(gptr) : "memory")
#define CP_COMMIT() asm volatile("cp.async.commit_group;" ::: "memory")

// ---------------------------------------------------------------------------
// fp32 -> fp16 converter (X + all three W in one launch).
// ---------------------------------------------------------------------------
__device__ __forceinline__ void cvt4(const float* __restrict__ src,
                                     __half* __restrict__ dst, size_t i)
{
    float4 v = ((const float4*)src)[i];
    __half2 a = __floats2half2_rn(v.x, v.y);
    __half2 b = __floats2half2_rn(v.z, v.w);
    uint2 u;
    u.x = *(const uint32_t*)&a;
    u.y = *(const uint32_t*)&b;
    ((uint2*)dst)[i] = u;
}

__global__ __launch_bounds__(256) void cvt_all_kernel(
    const float* __restrict__ X,  const float* __restrict__ Wq,
    const float* __restrict__ Wk, const float* __restrict__ Wv)
{
    int b = blockIdx.x;
    if (b < 2048) {
        cvt4(X, g_xh, (size_t)b * 256 + threadIdx.x);
    } else {
        b -= 2048;
        int w  = b >> 10;       // 1024 blocks per W
        int bb = b & 1023;
        const float* src = (w == 0) ? Wq : (w == 1) ? Wk : Wv;
        cvt4(src, g_wh[w], (size_t)bb * 256 + threadIdx.x);
    }
}

// ---------------------------------------------------------------------------
// Kernel 1: QKV projection, raw mma.sync + cp.async double-buffered stages.
// Yh = Xh @ Wh (M=2048, N=1024, K=1024), z selects W.
// BM=128, BN=64, BK=32, 32 K-stages. 8 warps (4 m x 2 n strips of 32 cols).
// ---------------------------------------------------------------------------
__global__ __launch_bounds__(256) void qkv_gemm_kernel()
{
    constexpr int BM = 128, BN = 64, BK = 32, NSTAGE = DM / BK;   // 32
    const __half* W = g_wh[blockIdx.z];
    __half*       Y = (blockIdx.z == 0) ? g_qh : (blockIdx.z == 1) ? g_kh : g_vh;

    __shared__ __align__(16) __half As[2][BM][BK + 8];   // 2 x 128 x 40
    __shared__ __align__(16) __half Bs[2][BK][BN + 8];   // 2 x 32 x 72

    const int tid  = threadIdx.x;
    const int warp = tid >> 5;
    const int lane = tid & 31;
    const int wm   = warp & 3;
    const int wn   = warp >> 2;

    const int row0 = blockIdx.y * BM;
    const int col0 = blockIdx.x * BN;

    float c[2][4][4];
    #pragma unroll
    for (int mi = 0; mi < 2; mi++)
        #pragma unroll
        for (int ni = 0; ni < 4; ni++)
            #pragma unroll
            for (int e = 0; e < 4; e++)
                c[mi][ni][e] = 0.0f;

    const uint32_t as0 = (uint32_t)__cvta_generic_to_shared(&As[0][0][0]);
    const uint32_t as1 = (uint32_t)__cvta_generic_to_shared(&As[1][0][0]);
    const uint32_t bs0 = (uint32_t)__cvta_generic_to_shared(&Bs[0][0][0]);
    const uint32_t bs1 = (uint32_t)__cvta_generic_to_shared(&Bs[1][0][0]);
    const int lrow = lane & 15;
    const int lk   = (lane >> 4) * 8;

    auto issue = [&](int stage, int buf) {
        const int k0 = stage * BK;
        const uint32_t ab = buf ? as1 : as0;
        const uint32_t bb = buf ? bs1 : bs0;
        #pragma unroll
        for (int it = 0; it < 2; it++) {          // A: 512 chunks of 16B
            int idx = tid + it * 256;
            int r = idx >> 2, cc = idx & 3;
            CP_ASYNC16(ab + (uint32_t)((r * (BK + 8) + cc * 8) * 2),
                       &g_xh[(size_t)(row0 + r) * DM + k0 + cc * 8]);
        }
        {                                          // B: 256 chunks of 16B
            int r = tid >> 3, cc = tid & 7;
            CP_ASYNC16(bb + (uint32_t)((r * (BN + 8) + cc * 8) * 2),
                       &W[(size_t)(k0 + r) * DM + col0 + cc * 8]);
        }
    };

    issue(0, 0);
    CP_COMMIT();

    for (int i = 0; i < NSTAGE; i++) {
        const int buf = i & 1;
        if (i + 1 < NSTAGE) {
            issue(i + 1, buf ^ 1);
            CP_COMMIT();
            asm volatile("cp.async.wait_group 1;" ::: "memory");
        } else {
            asm volatile("cp.async.wait_group 0;" ::: "memory");
        }
        __syncthreads();

        const uint32_t ab = buf ? as1 : as0;
        const uint32_t bb = buf ? bs1 : bs0;
        #pragma unroll
        for (int kk = 0; kk < BK; kk += 16) {
            uint32_t a[2][4];
            #pragma unroll
            for (int mi = 0; mi < 2; mi++) {
                uint32_t addr = ab + (uint32_t)(((wm * 32 + mi * 16 + lrow) * (BK + 8) + kk + lk) * 2);
                asm volatile(
                    "ldmatrix.sync.aligned.m8n8.x4.shared.b16 {%0,%1,%2,%3}, [%4];"
                    : "=r"(a[mi][0]), "=r"(a[mi][1]), "=r"(a[mi][2]), "=r"(a[mi][3])
                    : "r"(addr));
            }
            #pragma unroll
            for (int ni = 0; ni < 4; ni++) {
                uint32_t b0, b1;
                uint32_t addr = bb + (uint32_t)(((kk + lrow) * (BN + 8) + wn * 32 + ni * 8) * 2);
                asm volatile(
                    "ldmatrix.sync.aligned.m8n8.x2.trans.shared.b16 {%0,%1}, [%2];"
                    : "=r"(b0), "=r"(b1)
                    : "r"(addr));
                #pragma unroll
                for (int mi = 0; mi < 2; mi++) {
                    asm volatile(
                        "mma.sync.aligned.m16n8k16.row.col.f32.f16.f16.f32 "
                        "{%0,%1,%2,%3}, {%4,%5,%6,%7}, {%8,%9}, {%0,%1,%2,%3};"
                        : "+f"(c[mi][ni][0]), "+f"(c[mi][ni][1]),
                          "+f"(c[mi][ni][2]), "+f"(c[mi][ni][3])
                        : "r"(a[mi][0]), "r"(a[mi][1]), "r"(a[mi][2]), "r"(a[mi][3]),
                          "r"(b0), "r"(b1));
                }
            }
        }
        __syncthreads();
    }

    #pragma unroll
    for (int mi = 0; mi < 2; mi++) {
        int r0 = row0 + wm * 32 + mi * 16 + (lane >> 2);
        int r1 = r0 + 8;
        #pragma unroll
        for (int ni = 0; ni < 4; ni++) {
            int col = col0 + wn * 32 + ni * 8 + 2 * (lane & 3);
            __half2 lo = __floats2half2_rn(c[mi][ni][0], c[mi][ni][1]);
            __half2 hi = __floats2half2_rn(c[mi][ni][2], c[mi][ni][3]);
            *(__half2*)&Y[(size_t)r0 * DM + col] = lo;
            *(__half2*)&Y[(size_t)r1 * DM + col] = hi;
        }
    }
}

// ---------------------------------------------------------------------------
// Kernel 2: e = exp(q.k/8), raw mma.sync (unchanged from round 12).
// ---------------------------------------------------------------------------
__global__ __launch_bounds__(256) void scores_exp_kernel()
{
    const int h = blockIdx.z;
    __shared__ __align__(16) union {
        struct { __half Q[128][72]; __half K[128][72]; } in;
        __half E[128][136];
    } u;

    const int tid  = threadIdx.x;
    const int warp = tid >> 5;
    const int lane = tid & 31;
    const int wm   = warp & 3;
    const int wn   = warp >> 2;

    const int qrow0 = blockIdx.y * 128;
    const int krow0 = blockIdx.x * 128;
    const __half* qp = g_qh + h * HD;
    const __half* kp = g_kh + h * HD;

    #pragma unroll
    for (int it = 0; it < 4; it++) {
        int idx = tid + it * 256;
        int r = idx >> 3, c = idx & 7;
        *(int4*)&u.in.Q[r][c * 8] =
            *(const int4*)&qp[(size_t)(qrow0 + r) * DM + c * 8];
        *(int4*)&u.in.K[r][c * 8] =
            *(const int4*)&kp[(size_t)(krow0 + r) * DM + c * 8];
    }
    __syncthreads();

    float c[2][8][4];
    #pragma unroll
    for (int mi = 0; mi < 2; mi++)
        #pragma unroll
        for (int ni = 0; ni < 8; ni++)
            #pragma unroll
            for (int e = 0; e < 4; e++)
                c[mi][ni][e] = 0.0f;

    const uint32_t qs = (uint32_t)__cvta_generic_to_shared(&u.in.Q[0][0]);
    const uint32_t ks = (uint32_t)__cvta_generic_to_shared(&u.in.K[0][0]);
    const int lrow = lane & 15;
    const int lk   = (lane >> 4) * 8;

    #pragma unroll
    for (int kk = 0; kk < HD; kk += 16) {
        uint32_t a[2][4];
        #pragma unroll
        for (int mi = 0; mi < 2; mi++) {
            uint32_t addr = qs + (uint32_t)(((wm * 32 + mi * 16 + lrow) * 72 + kk + lk) * 2);
            asm volatile(
                "ldmatrix.sync.aligned.m8n8.x4.shared.b16 {%0,%1,%2,%3}, [%4];"
                : "=r"(a[mi][0]), "=r"(a[mi][1]), "=r"(a[mi][2]), "=r"(a[mi][3])
                : "r"(addr));
        }
        #pragma unroll
        for (int nb = 0; nb < 4; nb++) {
            uint32_t b0, b1, b2, b3;
            uint32_t addr = ks + (uint32_t)(((wn * 64 + nb * 16 + lrow) * 72 + kk + lk) * 2);
            asm volatile(
                "ldmatrix.sync.aligned.m8n8.x4.shared.b16 {%0,%1,%2,%3}, [%4];"
                : "=r"(b0), "=r"(b1), "=r"(b2), "=r"(b3)
                : "r"(addr));
            #pragma unroll
            for (int mi = 0; mi < 2; mi++) {
                asm volatile(
                    "mma.sync.aligned.m16n8k16.row.col.f32.f16.f16.f32 "
                    "{%0,%1,%2,%3}, {%4,%5,%6,%7}, {%8,%9}, {%0,%1,%2,%3};"
                    : "+f"(c[mi][2 * nb][0]), "+f"(c[mi][2 * nb][1]),
                      "+f"(c[mi][2 * nb][2]), "+f"(c[mi][2 * nb][3])
                    : "r"(a[mi][0]), "r"(a[mi][1]), "r"(a[mi][2]), "r"(a[mi][3]),
                      "r"(b0), "r"(b2));
                asm volatile(
                    "mma.sync.aligned.m16n8k16.row.col.f32.f16.f16.f32 "
                    "{%0,%1,%2,%3}, {%4,%5,%6,%7}, {%8,%9}, {%0,%1,%2,%3};"
                    : "+f"(c[mi][2 * nb + 1][0]), "+f"(c[mi][2 * nb + 1][1]),
                      "+f"(c[mi][2 * nb + 1][2]), "+f"(c[mi][2 * nb + 1][3])
                    : "r"(a[mi][0]), "r"(a[mi][1]), "r"(a[mi][2]), "r"(a[mi][3]),
                      "r"(b1), "r"(b3));
            }
        }
    }
    __syncthreads();

    #pragma unroll
    for (int mi = 0; mi < 2; mi++) {
        float sA = 0.0f, sB = 0.0f;
        #pragma unroll
        for (int ni = 0; ni < 8; ni++) {
            #pragma unroll
            for (int e = 0; e < 4; e++)
                c[mi][ni][e] = __expf(c[mi][ni][e] * 0.125f);
            sA += c[mi][ni][0] + c[mi][ni][1];
            sB += c[mi][ni][2] + c[mi][ni][3];
        }
        sA += __shfl_xor_sync(0xFFFFFFFFu, sA, 1);
        sA += __shfl_xor_sync(0xFFFFFFFFu, sA, 2);
        sB += __shfl_xor_sync(0xFFFFFFFFu, sB, 1);
        sB += __shfl_xor_sync(0xFFFFFFFFu, sB, 2);
        if ((lane & 3) == 0) {
            int r = wm * 32 + mi * 16 + (lane >> 2);
            g_psum[((size_t)h * S_LEN + qrow0 + r) * 32 + blockIdx.x * 2 + wn] = sA;
            g_psum[((size_t)h * S_LEN + qrow0 + r + 8) * 32 + blockIdx.x * 2 + wn] = sB;
        }
    }

    #pragma unroll
    for (int mi = 0; mi < 2; mi++)
        #pragma unroll
        for (int ni = 0; ni < 8; ni++) {
            int r   = wm * 32 + mi * 16 + (lane >> 2);
            int col = wn * 64 + ni * 8 + 2 * (lane & 3);
            __half2 lo = __floats2half2_rn(c[mi][ni][0], c[mi][ni][1]);
            __half2 hi = __floats2half2_rn(c[mi][ni][2], c[mi][ni][3]);
            *(__half2*)&u.E[r][col]     = lo;
            *(__half2*)&u.E[r + 8][col] = hi;
        }
    __syncthreads();

    __half* outp = g_eh + (size_t)h * S_LEN * S_LEN;
    #pragma unroll
    for (int it = 0; it < 8; it++) {
        int idx = tid + it * 256;
        int r = idx >> 4, cc = idx & 15;
        uint4 o = *(const uint4*)&u.E[r][cc * 8];
        *(uint4*)&outp[(size_t)(qrow0 + r) * S_LEN + krow0 + cc * 8] = o;
    }
}

// ---------------------------------------------------------------------------
// Kernel 3: rowsum -> reciprocal. Warp-per-row (coalesced 128B read + shfl).
// ---------------------------------------------------------------------------
__global__ __launch_bounds__(256) void rowsum_kernel()
{
    const int row  = blockIdx.x * 8 + (threadIdx.x >> 5);
    const int lane = threadIdx.x & 31;
    float s = g_psum[(size_t)row * 32 + lane];
    #pragma unroll
    for (int o = 16; o > 0; o >>= 1)
        s += __shfl_xor_sync(0xFFFFFFFFu, s, o);
    if (lane == 0)
        g_rinv[row] = 1.0f / s;
}

// ---------------------------------------------------------------------------
// Kernel 4: finalize probs with streaming (__stwt) stores.
// ---------------------------------------------------------------------------
__global__ __launch_bounds__(256) void finalize_kernel(float* __restrict__ probs)
{
    const size_t row = blockIdx.x;
    const float rinv = g_rinv[row];
    const uint4* src = (const uint4*)(g_eh + row * S_LEN);
    float4* dst = (float4*)(probs + row * S_LEN);
    const int tid = threadIdx.x;

    uint4 uv = src[tid];
    __half2 h0 = *(const __half2*)&uv.x;
    __half2 h1 = *(const __half2*)&uv.y;
    __half2 h2 = *(const __half2*)&uv.z;
    __half2 h3 = *(const __half2*)&uv.w;
    float2 f0 = __half22float2(h0);
    float2 f1 = __half22float2(h1);
    float2 f2 = __half22float2(h2);
    float2 f3 = __half22float2(h3);
    __stwt(&dst[2 * tid],
           make_float4(f0.x * rinv, f0.y * rinv, f1.x * rinv, f1.y * rinv));
    __stwt(&dst[2 * tid + 1],
           make_float4(f2.x * rinv, f2.y * rinv, f3.x * rinv, f3.y * rinv));
}

// ---------------------------------------------------------------------------
// Kernel 5: PV, raw mma.sync + cp.async double-buffered (unchanged from r15).
// ---------------------------------------------------------------------------
__global__ __launch_bounds__(256) void pv_kernel(float* __restrict__ ctx)
{
    constexpr int BM = 128, BK = 64, NSTAGE = S_LEN / BK;   // 32
    const int h = blockIdx.y;
    const __half* E  = g_eh + (size_t)h * S_LEN * S_LEN;
    const __half* vp = g_vh + h * HD;

    __shared__ __align__(16) __half Ps[2][BM][BK + 8];
    __shared__ __align__(16) __half Vs[2][BK][HD + 8];
    __shared__ float rinv[BM];

    const int tid  = threadIdx.x;
    const int warp = tid >> 5;
    const int lane = tid & 31;
    const int wm   = warp & 3;
    const int wn   = warp >> 2;
    const int row0 = blockIdx.x * BM;

    if (tid < BM)
        rinv[tid] = g_rinv[(size_t)h * S_LEN + row0 + tid];

    float c[2][4][4];
    #pragma unroll
    for (int mi = 0; mi < 2; mi++)
        #pragma unroll
        for (int ni = 0; ni < 4; ni++)
            #pragma unroll
            for (int e = 0; e < 4; e++)
                c[mi][ni][e] = 0.0f;

    const uint32_t ps0 = (uint32_t)__cvta_generic_to_shared(&Ps[0][0][0]);
    const uint32_t ps1 = (uint32_t)__cvta_generic_to_shared(&Ps[1][0][0]);
    const uint32_t vs0 = (uint32_t)__cvta_generic_to_shared(&Vs[0][0][0]);
    const uint32_t vs1 = (uint32_t)__cvta_generic_to_shared(&Vs[1][0][0]);
    const int lrow = lane & 15;
    const int lk   = (lane >> 4) * 8;

    auto issue = [&](int stage, int buf) {
        const int k0 = stage * BK;
        const uint32_t pb = buf ? ps1 : ps0;
        const uint32_t vb = buf ? vs1 : vs0;
        #pragma unroll
        for (int it = 0; it < 4; it++) {
            int idx = tid + it * 256;
            int r = idx >> 3, cc = idx & 7;
            CP_ASYNC16(pb + (uint32_t)((r * (BK + 8) + cc * 8) * 2),
                       &E[(size_t)(row0 + r) * S_LEN + k0 + cc * 8]);
        }
        #pragma unroll
        for (int it = 0; it < 2; it++) {
            int idx = tid + it * 256;
            int r = idx >> 3, cc = idx & 7;
            CP_ASYNC16(vb + (uint32_t)((r * (HD + 8) + cc * 8) * 2),
                       &vp[(size_t)(k0 + r) * DM + cc * 8]);
        }
    };

    issue(0, 0);
    CP_COMMIT();

    for (int i = 0; i < NSTAGE; i++) {
        const int buf = i & 1;
        if (i + 1 < NSTAGE) {
            issue(i + 1, buf ^ 1);
            CP_COMMIT();
            asm volatile("cp.async.wait_group 1;" ::: "memory");
        } else {
            asm volatile("cp.async.wait_group 0;" ::: "memory");
        }
        __syncthreads();

        const uint32_t pb = buf ? ps1 : ps0;
        const uint32_t vb = buf ? vs1 : vs0;
        #pragma unroll
        for (int kk = 0; kk < BK; kk += 16) {
            uint32_t a[2][4];
            #pragma unroll
            for (int mi = 0; mi < 2; mi++) {
                uint32_t addr = pb + (uint32_t)(((wm * 32 + mi * 16 + lrow) * (BK + 8) + kk + lk) * 2);
                asm volatile(
                    "ldmatrix.sync.aligned.m8n8.x4.shared.b16 {%0,%1,%2,%3}, [%4];"
                    : "=r"(a[mi][0]), "=r"(a[mi][1]), "=r"(a[mi][2]), "=r"(a[mi][3])
                    : "r"(addr));
            }
            #pragma unroll
            for (int ni = 0; ni < 4; ni++) {
                uint32_t b0, b1;
                uint32_t addr = vb + (uint32_t)(((kk + lrow) * (HD + 8) + wn * 32 + ni * 8) * 2);
                asm volatile(
                    "ldmatrix.sync.aligned.m8n8.x2.trans.shared.b16 {%0,%1}, [%2];"
                    : "=r"(b0), "=r"(b1)
                    : "r"(addr));
                #pragma unroll
                for (int mi = 0; mi < 2; mi++) {
                    asm volatile(
                        "mma.sync.aligned.m16n8k16.row.col.f32.f16.f16.f32 "
                        "{%0,%1,%2,%3}, {%4,%5,%6,%7}, {%8,%9}, {%0,%1,%2,%3};"
                        : "+f"(c[mi][ni][0]), "+f"(c[mi][ni][1]),
                          "+f"(c[mi][ni][2]), "+f"(c[mi][ni][3])
                        : "r"(a[mi][0]), "r"(a[mi][1]), "r"(a[mi][2]), "r"(a[mi][3]),
                          "r"(b0), "r"(b1));
                }
            }
        }
        __syncthreads();
    }

    #pragma unroll
    for (int mi = 0; mi < 2; mi++) {
        int rloc0 = wm * 32 + mi * 16 + (lane >> 2);
        int rloc1 = rloc0 + 8;
        float iv0 = rinv[rloc0];
        float iv1 = rinv[rloc1];
        #pragma unroll
        for (int ni = 0; ni < 4; ni++) {
            int col = h * HD + wn * 32 + ni * 8 + 2 * (lane & 3);
            *(float2*)&ctx[(size_t)(row0 + rloc0) * DM + col] =
                make_float2(c[mi][ni][0] * iv0, c[mi][ni][1] * iv0);
            *(float2*)&ctx[(size_t)(row0 + rloc1) * DM + col] =
                make_float2(c[mi][ni][2] * iv1, c[mi][ni][3] * iv1);
        }
    }
}

// ---------------------------------------------------------------------------
// Launch. d_out layout: context (2048*1024 floats) then probs (16*2048*2048).
// ---------------------------------------------------------------------------
extern "C" void kernel_launch(void* const* d_in, const int* in_sizes, int n_in,
                              void* d_out, int out_size)
{
    const float* hs = (const float*)d_in[0];
    const float* Wq = (const float*)d_in[1];
    const float* Wk = (const float*)d_in[2];
    const float* Wv = (const float*)d_in[3];

    float* ctx   = (float*)d_out;
    float* probs = ctx + (size_t)S_LEN * DM;

    cvt_all_kernel<<<dim3(5120), 256>>>(hs, Wq, Wk, Wv);
    qkv_gemm_kernel<<<dim3(DM / 64, S_LEN / 128, 3), 256>>>();
    scores_exp_kernel<<<dim3(S_LEN / 128, S_LEN / 128, NH), 256>>>();
    rowsum_kernel<<<dim3(NH * S_LEN / 8), 256>>>();
    pv_kernel<<<dim3(S_LEN / 128, NH), 256>>>(ctx);
    finalize_kernel<<<dim3(NH * S_LEN), 256>>>(probs);
}